// round 1
// baseline (speedup 1.0000x reference)
#include <cuda_runtime.h>
#include <cstdint>

// Problem constants
#define BATCH 4
#define SEQ   2048
#define EMB   1024
#define HID   2048
#define N1    (3*HID)          // 6144
#define MROWS (BATCH*SEQ)      // 8192

// GEMM tiling
#define BM 128
#define BN 128
#define BK 16
#define BKP 20   // padded smem row stride (floats) -> conflict-free

// Scratch (allocation-free rule: __device__ globals)
__device__ float g_Y[(size_t)MROWS * N1];   // 192 MB: [8192, 6144] = out1|z|h
__device__ float g_O[(size_t)MROWS * HID];  //  64 MB: gated output, GEMM2 input

__device__ __forceinline__ uint32_t f2tf(float f) {
    uint32_t u;
    asm("cvt.rna.tf32.f32 %0, %1;" : "=r"(u) : "f"(f));
    return u;
}

__device__ __forceinline__ void cp_async16(uint32_t saddr, const void* gptr) {
    asm volatile("cp.async.cg.shared.global [%0], [%1], 16;" :: "r"(saddr), "l"(gptr));
}

__device__ __forceinline__ void mma_tf32(float c[4], const uint32_t a[4], const uint32_t b[2]) {
    asm volatile(
        "mma.sync.aligned.m16n8k8.row.col.f32.tf32.tf32.f32 "
        "{%0,%1,%2,%3}, {%4,%5,%6,%7}, {%8,%9}, {%0,%1,%2,%3};"
        : "+f"(c[0]), "+f"(c[1]), "+f"(c[2]), "+f"(c[3])
        : "r"(a[0]), "r"(a[1]), "r"(a[2]), "r"(a[3]), "r"(b[0]), "r"(b[1]));
}

// C[M,N] = A[M,K] (row-major) * B[N,K]^T (row-major) -- both contiguous in K.
// Requires M%128==0, N%128==0, K%16==0 (true for all shapes here).
__global__ void __launch_bounds__(256, 1)
gemm_tn_tf32(const float* __restrict__ A, const float* __restrict__ B,
             float* __restrict__ C, int M, int N, int K) {
    __shared__ __align__(16) float As[2][BM * BKP];
    __shared__ __align__(16) float Bs[2][BN * BKP];

    const int tid  = threadIdx.x;
    const int lane = tid & 31;
    const int warp = tid >> 5;
    const int bm = blockIdx.y * BM;
    const int bn = blockIdx.x * BN;
    const int wm = (warp & 1) * 64;   // warp row offset within block tile
    const int wn = (warp >> 1) * 32;  // warp col offset within block tile
    const int g  = lane >> 2;         // group id 0..7
    const int t4 = lane & 3;          // 0..3

    float acc[4][4][4];
    #pragma unroll
    for (int i = 0; i < 4; i++)
        #pragma unroll
        for (int j = 0; j < 4; j++)
            #pragma unroll
            for (int r = 0; r < 4; r++) acc[i][j][r] = 0.f;

    auto load_stage = [&](int stage, int k0) {
        #pragma unroll
        for (int i = 0; i < 2; i++) {
            int ci  = tid + i * 256;          // 0..511 chunk (16B) index
            int row = ci >> 2;
            int cc  = (ci & 3) * 4;
            cp_async16(__cvta_generic_to_shared(&As[stage][row * BKP + cc]),
                       A + (size_t)(bm + row) * K + k0 + cc);
            cp_async16(__cvta_generic_to_shared(&Bs[stage][row * BKP + cc]),
                       B + (size_t)(bn + row) * K + k0 + cc);
        }
    };

    const int KT = K / BK;
    load_stage(0, 0);
    asm volatile("cp.async.commit_group;");

    for (int kt = 0; kt < KT; ++kt) {
        asm volatile("cp.async.wait_group 0;");
        __syncthreads();
        const int cur = kt & 1;
        if (kt + 1 < KT) {
            load_stage(cur ^ 1, (kt + 1) * BK);
            asm volatile("cp.async.commit_group;");
        }
        #pragma unroll
        for (int ks = 0; ks < 2; ++ks) {
            const int k0 = ks * 8;
            uint32_t af[4][4], bf[4][2];
            #pragma unroll
            for (int mi = 0; mi < 4; mi++) {
                const int r = wm + mi * 16 + g;
                af[mi][0] = f2tf(As[cur][(r)     * BKP + k0 + t4]);
                af[mi][1] = f2tf(As[cur][(r + 8) * BKP + k0 + t4]);
                af[mi][2] = f2tf(As[cur][(r)     * BKP + k0 + t4 + 4]);
                af[mi][3] = f2tf(As[cur][(r + 8) * BKP + k0 + t4 + 4]);
            }
            #pragma unroll
            for (int ni = 0; ni < 4; ni++) {
                const int r = wn + ni * 8 + g;
                bf[ni][0] = f2tf(Bs[cur][r * BKP + k0 + t4]);
                bf[ni][1] = f2tf(Bs[cur][r * BKP + k0 + t4 + 4]);
            }
            #pragma unroll
            for (int mi = 0; mi < 4; mi++)
                #pragma unroll
                for (int ni = 0; ni < 4; ni++)
                    mma_tf32(acc[mi][ni], af[mi], bf[ni]);
        }
        __syncthreads();
    }

    // Epilogue: c0/c1 row g, cols 2*t4, 2*t4+1 ; c2/c3 row g+8
    #pragma unroll
    for (int mi = 0; mi < 4; mi++) {
        #pragma unroll
        for (int ni = 0; ni < 4; ni++) {
            const size_t r0 = (size_t)(bm + wm + mi * 16 + g);
            const size_t c0 = (size_t)(bn + wn + ni * 8 + t4 * 2);
            C[r0 * N + c0]           = acc[mi][ni][0];
            C[r0 * N + c0 + 1]       = acc[mi][ni][1];
            C[(r0 + 8) * N + c0]     = acc[mi][ni][2];
            C[(r0 + 8) * N + c0 + 1] = acc[mi][ni][3];
        }
    }
}

// Fused: causal depthwise conv(K=4) -> sigmoid -> linear scan -> silu(out1)*h
// One thread per (batch, channel). Warp covers 32 consecutive channels -> coalesced.
__global__ void __launch_bounds__(128)
scan_kernel(const float* __restrict__ cw, float* __restrict__ O) {
    const int gid = blockIdx.x * blockDim.x + threadIdx.x;  // 0..8191
    const int b = gid >> 11;
    const int c = gid & (HID - 1);

    const float w0 = cw[c * 4 + 0], w1 = cw[c * 4 + 1];
    const float w2 = cw[c * 4 + 2], w3 = cw[c * 4 + 3];

    const float* Yb = g_Y + (size_t)b * SEQ * N1;
    const float* o1p = Yb + c;
    const float* zp  = Yb + HID + c;
    const float* hp  = Yb + 2 * HID + c;
    float* outp = O + (size_t)b * SEQ * HID + c;

    float z1 = 0.f, z2 = 0.f, z3 = 0.f;  // z[s-1], z[s-2], z[s-3]
    float h = 0.f;
    #pragma unroll 4
    for (int s = 0; s < SEQ; ++s) {
        const size_t off = (size_t)s * N1;
        const float zr  = zp[off];
        const float hin = hp[off];
        const float o1  = o1p[off];
        const float cv  = w0 * z3 + w1 * z2 + w2 * z1 + w3 * zr;
        z3 = z2; z2 = z1; z1 = zr;
        const float zt = 1.f / (1.f + __expf(-cv));
        h = fmaf(zt, hin - h, h);                       // h = (1-z)h + z*hin
        const float sil = o1 * (1.f / (1.f + __expf(-o1)));
        outp[(size_t)s * HID] = sil * h;
    }
}

extern "C" void kernel_launch(void* const* d_in, const int* in_sizes, int n_in,
                              void* d_out, int out_size) {
    const float* x  = (const float*)d_in[0];   // [4,2048,1024]
    const float* w1 = (const float*)d_in[1];   // [6144,1024]
    const float* w2 = (const float*)d_in[2];   // [1024,2048]
    const float* cw = (const float*)d_in[3];   // [2048,4]
    float* out = (float*)d_out;                // [4,2048,1024]

    float *Y, *O;
    cudaGetSymbolAddress((void**)&Y, g_Y);
    cudaGetSymbolAddress((void**)&O, g_O);

    // GEMM1: Y[8192,6144] = x[8192,1024] @ w1^T
    dim3 g1(N1 / BN, MROWS / BM);
    gemm_tn_tf32<<<g1, 256>>>(x, w1, Y, MROWS, N1, EMB);

    // Fused conv + sigmoid + scan + silu-gate -> O[8192,2048]
    scan_kernel<<<(BATCH * HID) / 128, 128>>>(cw, O);

    // GEMM2: out[8192,1024] = O[8192,2048] @ w2^T
    dim3 g2(EMB / BN, MROWS / BM);
    gemm_tn_tf32<<<g2, 256>>>(O, w2, out, MROWS, EMB, HID);
}

// round 2
// speedup vs baseline: 1.8720x; 1.8720x over previous
#include <cuda_runtime.h>
#include <cstdint>

// Problem constants
#define BATCH 4
#define SEQ   2048
#define EMB   1024
#define HID   2048
#define N1    (3*HID)          // 6144
#define MROWS (BATCH*SEQ)      // 8192
#define BC    (BATCH*HID)      // 8192 (batch*channel lanes)
#define NC    32               // scan chunks
#define CL    (SEQ/NC)         // 64 steps per chunk

// GEMM tiling
#define BM 128
#define BN 128
#define BK 16
#define BKP 20   // padded smem row stride (floats) -> conflict-free

// Scratch (allocation-free rule: __device__ globals)
__device__ float g_Y[(size_t)MROWS * N1];   // 192 MB: [8192, 6144] = out1|z|h
__device__ float g_O[(size_t)MROWS * HID];  //  64 MB: gated output, GEMM2 input
__device__ float g_A[NC * BC];              // chunk decay products
__device__ float g_B[NC * BC];              // chunk offsets
__device__ float g_H[NC * BC];              // per-chunk initial h

__device__ __forceinline__ uint32_t f2tf(float f) {
    uint32_t u;
    asm("cvt.rna.tf32.f32 %0, %1;" : "=r"(u) : "f"(f));
    return u;
}

__device__ __forceinline__ void cp_async16(uint32_t saddr, const void* gptr) {
    asm volatile("cp.async.cg.shared.global [%0], [%1], 16;" :: "r"(saddr), "l"(gptr));
}

__device__ __forceinline__ void mma_tf32(float c[4], const uint32_t a[4], const uint32_t b[2]) {
    asm volatile(
        "mma.sync.aligned.m16n8k8.row.col.f32.tf32.tf32.f32 "
        "{%0,%1,%2,%3}, {%4,%5,%6,%7}, {%8,%9}, {%0,%1,%2,%3};"
        : "+f"(c[0]), "+f"(c[1]), "+f"(c[2]), "+f"(c[3])
        : "r"(a[0]), "r"(a[1]), "r"(a[2]), "r"(a[3]), "r"(b[0]), "r"(b[1]));
}

__device__ __forceinline__ float sigmoidf_fast(float x) {
    return 1.f / (1.f + __expf(-x));
}

// C[M,N] = A[M,K] (row-major) * B[N,K]^T (row-major) -- both contiguous in K.
__global__ void __launch_bounds__(256, 1)
gemm_tn_tf32(const float* __restrict__ A, const float* __restrict__ B,
             float* __restrict__ C, int M, int N, int K) {
    __shared__ __align__(16) float As[2][BM * BKP];
    __shared__ __align__(16) float Bs[2][BN * BKP];

    const int tid  = threadIdx.x;
    const int lane = tid & 31;
    const int warp = tid >> 5;
    const int bm = blockIdx.y * BM;
    const int bn = blockIdx.x * BN;
    const int wm = (warp & 1) * 64;
    const int wn = (warp >> 1) * 32;
    const int g  = lane >> 2;
    const int t4 = lane & 3;

    float acc[4][4][4];
    #pragma unroll
    for (int i = 0; i < 4; i++)
        #pragma unroll
        for (int j = 0; j < 4; j++)
            #pragma unroll
            for (int r = 0; r < 4; r++) acc[i][j][r] = 0.f;

    auto load_stage = [&](int stage, int k0) {
        #pragma unroll
        for (int i = 0; i < 2; i++) {
            int ci  = tid + i * 256;
            int row = ci >> 2;
            int cc  = (ci & 3) * 4;
            cp_async16(__cvta_generic_to_shared(&As[stage][row * BKP + cc]),
                       A + (size_t)(bm + row) * K + k0 + cc);
            cp_async16(__cvta_generic_to_shared(&Bs[stage][row * BKP + cc]),
                       B + (size_t)(bn + row) * K + k0 + cc);
        }
    };

    const int KT = K / BK;
    load_stage(0, 0);
    asm volatile("cp.async.commit_group;");

    for (int kt = 0; kt < KT; ++kt) {
        asm volatile("cp.async.wait_group 0;");
        __syncthreads();
        const int cur = kt & 1;
        if (kt + 1 < KT) {
            load_stage(cur ^ 1, (kt + 1) * BK);
            asm volatile("cp.async.commit_group;");
        }
        #pragma unroll
        for (int ks = 0; ks < 2; ++ks) {
            const int k0 = ks * 8;
            uint32_t af[4][4], bf[4][2];
            #pragma unroll
            for (int mi = 0; mi < 4; mi++) {
                const int r = wm + mi * 16 + g;
                af[mi][0] = f2tf(As[cur][(r)     * BKP + k0 + t4]);
                af[mi][1] = f2tf(As[cur][(r + 8) * BKP + k0 + t4]);
                af[mi][2] = f2tf(As[cur][(r)     * BKP + k0 + t4 + 4]);
                af[mi][3] = f2tf(As[cur][(r + 8) * BKP + k0 + t4 + 4]);
            }
            #pragma unroll
            for (int ni = 0; ni < 4; ni++) {
                const int r = wn + ni * 8 + g;
                bf[ni][0] = f2tf(Bs[cur][r * BKP + k0 + t4]);
                bf[ni][1] = f2tf(Bs[cur][r * BKP + k0 + t4 + 4]);
            }
            #pragma unroll
            for (int mi = 0; mi < 4; mi++)
                #pragma unroll
                for (int ni = 0; ni < 4; ni++)
                    mma_tf32(acc[mi][ni], af[mi], bf[ni]);
        }
        __syncthreads();
    }

    #pragma unroll
    for (int mi = 0; mi < 4; mi++) {
        #pragma unroll
        for (int ni = 0; ni < 4; ni++) {
            const size_t r0 = (size_t)(bm + wm + mi * 16 + g);
            const size_t c0 = (size_t)(bn + wn + ni * 8 + t4 * 2);
            C[r0 * N + c0]           = acc[mi][ni][0];
            C[r0 * N + c0 + 1]       = acc[mi][ni][1];
            C[(r0 + 8) * N + c0]     = acc[mi][ni][2];
            C[(r0 + 8) * N + c0 + 1] = acc[mi][ni][3];
        }
    }
}

// ── Chunked scan, pass 1: per-(bc, chunk) affine summary (A = prod a, B) ──
__global__ void __launch_bounds__(256)
scan_pass1(const float* __restrict__ cw) {
    const int gid   = blockIdx.x * blockDim.x + threadIdx.x; // 0..BC*NC-1
    const int bc    = gid & (BC - 1);
    const int chunk = gid >> 13;
    const int b = bc >> 11;
    const int c = bc & (HID - 1);

    const float w0 = cw[c * 4 + 0], w1 = cw[c * 4 + 1];
    const float w2 = cw[c * 4 + 2], w3 = cw[c * 4 + 3];

    const float* Yb = g_Y + (size_t)b * SEQ * N1;
    const float* zp = Yb + HID + c;
    const float* hp = Yb + 2 * HID + c;

    const int s0 = chunk * CL;
    float z1 = 0.f, z2 = 0.f, z3 = 0.f;
    if (chunk > 0) {
        z1 = zp[(size_t)(s0 - 1) * N1];
        z2 = zp[(size_t)(s0 - 2) * N1];
        z3 = zp[(size_t)(s0 - 3) * N1];
    }
    float A = 1.f, B = 0.f;
    #pragma unroll 4
    for (int s = s0; s < s0 + CL; ++s) {
        const size_t off = (size_t)s * N1;
        const float zr  = zp[off];
        const float hin = hp[off];
        const float cv  = w0 * z3 + w1 * z2 + w2 * z1 + w3 * zr;
        z3 = z2; z2 = z1; z1 = zr;
        const float zt = sigmoidf_fast(cv);
        const float a  = 1.f - zt;
        A *= a;
        B = fmaf(a, B, zt * hin);
    }
    g_A[chunk * BC + bc] = A;
    g_B[chunk * BC + bc] = B;
}

// ── Cross-chunk prefix: h_init per chunk ──
__global__ void __launch_bounds__(256)
scan_combine() {
    const int bc = blockIdx.x * blockDim.x + threadIdx.x; // 0..BC-1
    float h = 0.f;
    #pragma unroll
    for (int i = 0; i < NC; ++i) {
        g_H[i * BC + bc] = h;
        h = fmaf(g_A[i * BC + bc], h, g_B[i * BC + bc]);
    }
}

// ── Pass 2: re-run scan from h_init, gate with silu(out1), write O ──
__global__ void __launch_bounds__(256)
scan_pass2(const float* __restrict__ cw, float* __restrict__ O) {
    const int gid   = blockIdx.x * blockDim.x + threadIdx.x;
    const int bc    = gid & (BC - 1);
    const int chunk = gid >> 13;
    const int b = bc >> 11;
    const int c = bc & (HID - 1);

    const float w0 = cw[c * 4 + 0], w1 = cw[c * 4 + 1];
    const float w2 = cw[c * 4 + 2], w3 = cw[c * 4 + 3];

    const float* Yb = g_Y + (size_t)b * SEQ * N1;
    const float* o1p = Yb + c;
    const float* zp  = Yb + HID + c;
    const float* hp  = Yb + 2 * HID + c;
    float* outp = O + (size_t)b * SEQ * HID + c;

    const int s0 = chunk * CL;
    float z1 = 0.f, z2 = 0.f, z3 = 0.f;
    if (chunk > 0) {
        z1 = zp[(size_t)(s0 - 1) * N1];
        z2 = zp[(size_t)(s0 - 2) * N1];
        z3 = zp[(size_t)(s0 - 3) * N1];
    }
    float h = g_H[chunk * BC + bc];
    #pragma unroll 4
    for (int s = s0; s < s0 + CL; ++s) {
        const size_t off = (size_t)s * N1;
        const float zr  = zp[off];
        const float hin = hp[off];
        const float o1  = o1p[off];
        const float cv  = w0 * z3 + w1 * z2 + w2 * z1 + w3 * zr;
        z3 = z2; z2 = z1; z1 = zr;
        const float zt = sigmoidf_fast(cv);
        h = fmaf(zt, hin - h, h);
        const float sil = o1 * sigmoidf_fast(o1);
        outp[(size_t)s * HID] = sil * h;
    }
}

extern "C" void kernel_launch(void* const* d_in, const int* in_sizes, int n_in,
                              void* d_out, int out_size) {
    const float* x  = (const float*)d_in[0];   // [4,2048,1024]
    const float* w1 = (const float*)d_in[1];   // [6144,1024]
    const float* w2 = (const float*)d_in[2];   // [1024,2048]
    const float* cw = (const float*)d_in[3];   // [2048,4]
    float* out = (float*)d_out;                // [4,2048,1024]

    float *Y, *O;
    cudaGetSymbolAddress((void**)&Y, g_Y);
    cudaGetSymbolAddress((void**)&O, g_O);

    // GEMM1: Y[8192,6144] = x[8192,1024] @ w1^T
    dim3 g1(N1 / BN, MROWS / BM);
    gemm_tn_tf32<<<g1, 256>>>(x, w1, Y, MROWS, N1, EMB);

    // Chunked scan (3 kernels)
    scan_pass1<<<(BC * NC) / 256, 256>>>(cw);
    scan_combine<<<BC / 256, 256>>>();
    scan_pass2<<<(BC * NC) / 256, 256>>>(cw, O);

    // GEMM2: out[8192,1024] = O[8192,2048] @ w2^T
    dim3 g2(EMB / BN, MROWS / BM);
    gemm_tn_tf32<<<g2, 256>>>(O, w2, out, MROWS, EMB, HID);
}

// round 6
// speedup vs baseline: 2.0419x; 1.0908x over previous
#include <cuda_runtime.h>
#include <cstdint>

// Problem constants
#define BATCH 4
#define SEQ   2048
#define EMB   1024
#define HID   2048
#define N1    (3*HID)          // 6144
#define MROWS (BATCH*SEQ)      // 8192
#define BC    (BATCH*HID)      // 8192
#define NC    32               // scan chunks
#define CL    (SEQ/NC)         // 64

// GEMM tiling
#define BM 128
#define BN 128
#define BK 16
#define BKP 20                 // padded smem row stride (floats)
#define NSTAGE 3
#define STAGE_WORDS (BM * BKP) // per-operand words per stage (10240 B)
#define SMEM_DYN (NSTAGE * 2 * STAGE_WORDS * 4)   // 61440 B

// Scratch (allocation-free rule: __device__ globals)
__device__ float    g_Y[(size_t)MROWS * N1];   // GEMM1 out (f32)
__device__ uint32_t g_O[(size_t)MROWS * HID];  // gated output, tf32 bits
__device__ uint32_t g_X[(size_t)MROWS * EMB];  // x in tf32
__device__ uint32_t g_W1[(size_t)N1 * EMB];    // w1 in tf32
__device__ uint32_t g_W2[(size_t)EMB * HID];   // w2 in tf32
__device__ float g_A[NC * BC];
__device__ float g_B[NC * BC];
__device__ float g_H[NC * BC];

__device__ __forceinline__ uint32_t f2tf(float f) {
    uint32_t u;
    asm("cvt.rna.tf32.f32 %0, %1;" : "=r"(u) : "f"(f));
    return u;
}
__device__ __forceinline__ void cp_async16(uint32_t saddr, const void* gptr) {
    asm volatile("cp.async.cg.shared.global [%0], [%1], 16;" :: "r"(saddr), "l"(gptr));
}
__device__ __forceinline__ void mma_tf32(float c[4], const uint32_t a[4], const uint32_t b[2]) {
    asm volatile(
        "mma.sync.aligned.m16n8k8.row.col.f32.tf32.tf32.f32 "
        "{%0,%1,%2,%3}, {%4,%5,%6,%7}, {%8,%9}, {%0,%1,%2,%3};"
        : "+f"(c[0]), "+f"(c[1]), "+f"(c[2]), "+f"(c[3])
        : "r"(a[0]), "r"(a[1]), "r"(a[2]), "r"(a[3]), "r"(b[0]), "r"(b[1]));
}
__device__ __forceinline__ float sigmoidf_fast(float x) {
    return 1.f / (1.f + __expf(-x));
}

// ── f32 -> tf32 bulk convert (float4) ───────────────────────────────────
__global__ void __launch_bounds__(256)
cvt_tf32_kernel(const float4* __restrict__ in, uint4* __restrict__ out, int n4) {
    int i = blockIdx.x * blockDim.x + threadIdx.x;
    if (i < n4) {
        float4 v = in[i];
        uint4 o;
        o.x = f2tf(v.x); o.y = f2tf(v.y); o.z = f2tf(v.z); o.w = f2tf(v.w);
        out[i] = o;
    }
}

// ── tf32 GEMM: C[M,N] = A[M,K] · B[N,K]^T, operands pre-converted tf32 ──
__global__ void __launch_bounds__(256, 2)
gemm_tn_tf32(const uint32_t* __restrict__ A, const uint32_t* __restrict__ B,
             float* __restrict__ C, int M, int N, int K) {
    extern __shared__ __align__(16) uint32_t sm[];
    // layout: [stage][A:STAGE_WORDS | B:STAGE_WORDS]
    const int tid  = threadIdx.x;
    const int lane = tid & 31;
    const int warp = tid >> 5;
    const int bm = blockIdx.y * BM;
    const int bn = blockIdx.x * BN;
    const int wm = (warp & 1) * 64;
    const int wn = (warp >> 1) * 32;
    const int g  = lane >> 2;
    const int t4 = lane & 3;

    float acc[4][4][4];
    #pragma unroll
    for (int i = 0; i < 4; i++)
        #pragma unroll
        for (int j = 0; j < 4; j++)
            #pragma unroll
            for (int r = 0; r < 4; r++) acc[i][j][r] = 0.f;

    auto load_stage = [&](int stage, int k0) {
        uint32_t* As = sm + stage * 2 * STAGE_WORDS;
        uint32_t* Bs = As + STAGE_WORDS;
        #pragma unroll
        for (int i = 0; i < 2; i++) {
            int ci  = tid + i * 256;          // 0..511 chunk (16B) index
            int row = ci >> 2;
            int cc  = (ci & 3) * 4;
            cp_async16(__cvta_generic_to_shared(&As[row * BKP + cc]),
                       A + (size_t)(bm + row) * K + k0 + cc);
            cp_async16(__cvta_generic_to_shared(&Bs[row * BKP + cc]),
                       B + (size_t)(bn + row) * K + k0 + cc);
        }
        asm volatile("cp.async.commit_group;");
    };

    const int KT = K / BK;
    load_stage(0, 0);
    load_stage(1, BK);

    for (int kt = 0; kt < KT; ++kt) {
        asm volatile("cp.async.wait_group 1;");
        __syncthreads();
        const int cur = kt % NSTAGE;
        if (kt + 2 < KT) load_stage((kt + 2) % NSTAGE, (kt + 2) * BK);

        const uint32_t* As = sm + cur * 2 * STAGE_WORDS;
        const uint32_t* Bs = As + STAGE_WORDS;
        #pragma unroll
        for (int ks = 0; ks < 2; ++ks) {
            const int k0 = ks * 8;
            uint32_t af[4][4], bf[4][2];
            #pragma unroll
            for (int mi = 0; mi < 4; mi++) {
                const int r = wm + mi * 16 + g;
                af[mi][0] = As[(r)     * BKP + k0 + t4];
                af[mi][1] = As[(r + 8) * BKP + k0 + t4];
                af[mi][2] = As[(r)     * BKP + k0 + t4 + 4];
                af[mi][3] = As[(r + 8) * BKP + k0 + t4 + 4];
            }
            #pragma unroll
            for (int ni = 0; ni < 4; ni++) {
                const int r = wn + ni * 8 + g;
                bf[ni][0] = Bs[r * BKP + k0 + t4];
                bf[ni][1] = Bs[r * BKP + k0 + t4 + 4];
            }
            #pragma unroll
            for (int mi = 0; mi < 4; mi++)
                #pragma unroll
                for (int ni = 0; ni < 4; ni++)
                    mma_tf32(acc[mi][ni], af[mi], bf[ni]);
        }
        __syncthreads();
    }

    #pragma unroll
    for (int mi = 0; mi < 4; mi++) {
        #pragma unroll
        for (int ni = 0; ni < 4; ni++) {
            const size_t r0 = (size_t)(bm + wm + mi * 16 + g);
            const size_t c0 = (size_t)(bn + wn + ni * 8 + t4 * 2);
            *reinterpret_cast<float2*>(C + r0 * N + c0) =
                make_float2(acc[mi][ni][0], acc[mi][ni][1]);
            *reinterpret_cast<float2*>(C + (r0 + 8) * N + c0) =
                make_float2(acc[mi][ni][2], acc[mi][ni][3]);
        }
    }
}

// ── Chunked scan ────────────────────────────────────────────────────────
__global__ void __launch_bounds__(256)
scan_pass1(const float* __restrict__ cw) {
    const int gid   = blockIdx.x * blockDim.x + threadIdx.x;
    const int bc    = gid & (BC - 1);
    const int chunk = gid >> 13;
    const int b = bc >> 11;
    const int c = bc & (HID - 1);

    const float w0 = cw[c * 4 + 0], w1 = cw[c * 4 + 1];
    const float w2 = cw[c * 4 + 2], w3 = cw[c * 4 + 3];

    const float* Yb = g_Y + (size_t)b * SEQ * N1;
    const float* zp = Yb + HID + c;
    const float* hp = Yb + 2 * HID + c;

    const int s0 = chunk * CL;
    float z1 = 0.f, z2 = 0.f, z3 = 0.f;
    if (chunk > 0) {
        z1 = zp[(size_t)(s0 - 1) * N1];
        z2 = zp[(size_t)(s0 - 2) * N1];
        z3 = zp[(size_t)(s0 - 3) * N1];
    }
    float A = 1.f, B = 0.f;
    #pragma unroll 4
    for (int s = s0; s < s0 + CL; ++s) {
        const size_t off = (size_t)s * N1;
        const float zr  = zp[off];
        const float hin = hp[off];
        const float cv  = w0 * z3 + w1 * z2 + w2 * z1 + w3 * zr;
        z3 = z2; z2 = z1; z1 = zr;
        const float zt = sigmoidf_fast(cv);
        const float a  = 1.f - zt;
        A *= a;
        B = fmaf(a, B, zt * hin);
    }
    g_A[chunk * BC + bc] = A;
    g_B[chunk * BC + bc] = B;
}

__global__ void __launch_bounds__(256)
scan_combine() {
    const int bc = blockIdx.x * blockDim.x + threadIdx.x;
    float h = 0.f;
    #pragma unroll
    for (int i = 0; i < NC; ++i) {
        g_H[i * BC + bc] = h;
        h = fmaf(g_A[i * BC + bc], h, g_B[i * BC + bc]);
    }
}

__global__ void __launch_bounds__(256)
scan_pass2(const float* __restrict__ cw, uint32_t* __restrict__ O) {
    const int gid   = blockIdx.x * blockDim.x + threadIdx.x;
    const int bc    = gid & (BC - 1);
    const int chunk = gid >> 13;
    const int b = bc >> 11;
    const int c = bc & (HID - 1);

    const float w0 = cw[c * 4 + 0], w1 = cw[c * 4 + 1];
    const float w2 = cw[c * 4 + 2], w3 = cw[c * 4 + 3];

    const float* Yb = g_Y + (size_t)b * SEQ * N1;
    const float* o1p = Yb + c;
    const float* zp  = Yb + HID + c;
    const float* hp  = Yb + 2 * HID + c;
    uint32_t* outp = O + (size_t)b * SEQ * HID + c;

    const int s0 = chunk * CL;
    float z1 = 0.f, z2 = 0.f, z3 = 0.f;
    if (chunk > 0) {
        z1 = zp[(size_t)(s0 - 1) * N1];
        z2 = zp[(size_t)(s0 - 2) * N1];
        z3 = zp[(size_t)(s0 - 3) * N1];
    }
    float h = g_H[chunk * BC + bc];
    #pragma unroll 4
    for (int s = s0; s < s0 + CL; ++s) {
        const size_t off = (size_t)s * N1;
        const float zr  = zp[off];
        const float hin = hp[off];
        const float o1  = o1p[off];
        const float cv  = w0 * z3 + w1 * z2 + w2 * z1 + w3 * zr;
        z3 = z2; z2 = z1; z1 = zr;
        const float zt = sigmoidf_fast(cv);
        h = fmaf(zt, hin - h, h);
        const float sil = o1 * sigmoidf_fast(o1);
        outp[(size_t)s * HID] = f2tf(sil * h);   // tf32 bits for GEMM2
    }
}

extern "C" void kernel_launch(void* const* d_in, const int* in_sizes, int n_in,
                              void* d_out, int out_size) {
    const float* x  = (const float*)d_in[0];   // [4,2048,1024]
    const float* w1 = (const float*)d_in[1];   // [6144,1024]
    const float* w2 = (const float*)d_in[2];   // [1024,2048]
    const float* cw = (const float*)d_in[3];   // [2048,4]
    float* out = (float*)d_out;                // [4,2048,1024]

    float *Y;
    uint32_t *O, *X, *W1, *W2;
    cudaGetSymbolAddress((void**)&Y,  g_Y);
    cudaGetSymbolAddress((void**)&O,  g_O);
    cudaGetSymbolAddress((void**)&X,  g_X);
    cudaGetSymbolAddress((void**)&W1, g_W1);
    cudaGetSymbolAddress((void**)&W2, g_W2);

    static bool attr_set = false;
    if (!attr_set) {
        cudaFuncSetAttribute(gemm_tn_tf32,
                             cudaFuncAttributeMaxDynamicSharedMemorySize, SMEM_DYN);
        attr_set = true;
    }

    // Pre-convert GEMM operands to tf32
    {
        int n4;
        n4 = (MROWS * EMB) / 4;
        cvt_tf32_kernel<<<(n4 + 255) / 256, 256>>>((const float4*)x,  (uint4*)X,  n4);
        n4 = (N1 * EMB) / 4;
        cvt_tf32_kernel<<<(n4 + 255) / 256, 256>>>((const float4*)w1, (uint4*)W1, n4);
        n4 = (EMB * HID) / 4;
        cvt_tf32_kernel<<<(n4 + 255) / 256, 256>>>((const float4*)w2, (uint4*)W2, n4);
    }

    // GEMM1: Y[8192,6144] = x @ w1^T
    dim3 g1(N1 / BN, MROWS / BM);
    gemm_tn_tf32<<<g1, 256, SMEM_DYN>>>(X, W1, Y, MROWS, N1, EMB);

    // Chunked scan
    scan_pass1<<<(BC * NC) / 256, 256>>>(cw);
    scan_combine<<<BC / 256, 256>>>();
    scan_pass2<<<(BC * NC) / 256, 256>>>(cw, O);

    // GEMM2: out[8192,1024] = O @ w2^T
    dim3 g2(EMB / BN, MROWS / BM);
    gemm_tn_tf32<<<g2, 256, SMEM_DYN>>>(O, W2, out, MROWS, EMB, HID);
}

// round 11
// speedup vs baseline: 2.0626x; 1.0101x over previous
#include <cuda_runtime.h>
#include <cstdint>

// Problem constants
#define BATCH 4
#define SEQ   2048
#define EMB   1024
#define HID   2048
#define N1    (3*HID)          // 6144
#define MROWS (BATCH*SEQ)      // 8192
#define BC    (BATCH*HID)      // 8192
#define NC    32               // scan chunks
#define CL    (SEQ/NC)         // 64
#define BC4   (BC/4)           // 2048 vector lanes

// GEMM tiling
#define BM 128
#define BN 128
#define BK 16
#define BKP 20                 // padded smem row stride (words)
#define NSTAGE 3
#define STAGE_WORDS (BM * BKP)
#define SMEM_DYN (NSTAGE * 2 * STAGE_WORDS * 4)   // 61440 B

// Scratch (allocation-free rule: __device__ globals)
__device__ float    g_Y[(size_t)MROWS * N1];
__device__ uint32_t g_O[(size_t)MROWS * HID];  // tf32 bits
__device__ uint32_t g_X[(size_t)MROWS * EMB];
__device__ uint32_t g_W1[(size_t)N1 * EMB];
__device__ uint32_t g_W2[(size_t)EMB * HID];
__device__ float g_A[NC * BC];
__device__ float g_B[NC * BC];
__device__ float g_H[NC * BC];

__device__ __forceinline__ uint32_t f2tf(float f) {
    uint32_t u;
    asm("cvt.rna.tf32.f32 %0, %1;" : "=r"(u) : "f"(f));
    return u;
}
__device__ __forceinline__ void cp_async16(uint32_t saddr, const void* gptr) {
    asm volatile("cp.async.cg.shared.global [%0], [%1], 16;" :: "r"(saddr), "l"(gptr));
}
__device__ __forceinline__ void mma_tf32(float c[4], const uint32_t a[4], const uint32_t b[2]) {
    asm volatile(
        "mma.sync.aligned.m16n8k8.row.col.f32.tf32.tf32.f32 "
        "{%0,%1,%2,%3}, {%4,%5,%6,%7}, {%8,%9}, {%0,%1,%2,%3};"
        : "+f"(c[0]), "+f"(c[1]), "+f"(c[2]), "+f"(c[3])
        : "r"(a[0]), "r"(a[1]), "r"(a[2]), "r"(a[3]), "r"(b[0]), "r"(b[1]));
}
__device__ __forceinline__ float sigmoidf_fast(float x) {
    return 1.f / (1.f + __expf(-x));
}

// ── f32 -> tf32 bulk convert ────────────────────────────────────────────
__global__ void __launch_bounds__(256)
cvt_tf32_kernel(const float4* __restrict__ in, uint4* __restrict__ out, int n4) {
    int i = blockIdx.x * blockDim.x + threadIdx.x;
    if (i < n4) {
        float4 v = in[i];
        uint4 o;
        o.x = f2tf(v.x); o.y = f2tf(v.y); o.z = f2tf(v.z); o.w = f2tf(v.w);
        out[i] = o;
    }
}

// ── tf32 GEMM: C[M,N] = A[M,K] · B[N,K]^T ───────────────────────────────
__global__ void __launch_bounds__(256, 2)
gemm_tn_tf32(const uint32_t* __restrict__ A, const uint32_t* __restrict__ B,
             float* __restrict__ C, int M, int N, int K) {
    extern __shared__ __align__(16) uint32_t sm[];
    const int tid  = threadIdx.x;
    const int lane = tid & 31;
    const int warp = tid >> 5;
    const int bm = blockIdx.y * BM;
    const int bn = blockIdx.x * BN;
    const int wm = (warp & 1) * 64;
    const int wn = (warp >> 1) * 32;
    const int g  = lane >> 2;
    const int t4 = lane & 3;

    float acc[4][4][4];
    #pragma unroll
    for (int i = 0; i < 4; i++)
        #pragma unroll
        for (int j = 0; j < 4; j++)
            #pragma unroll
            for (int r = 0; r < 4; r++) acc[i][j][r] = 0.f;

    auto load_stage = [&](int stage, int k0) {
        uint32_t* As = sm + stage * 2 * STAGE_WORDS;
        uint32_t* Bs = As + STAGE_WORDS;
        #pragma unroll
        for (int i = 0; i < 2; i++) {
            int ci  = tid + i * 256;
            int row = ci >> 2;
            int cc  = (ci & 3) * 4;
            cp_async16(__cvta_generic_to_shared(&As[row * BKP + cc]),
                       A + (size_t)(bm + row) * K + k0 + cc);
            cp_async16(__cvta_generic_to_shared(&Bs[row * BKP + cc]),
                       B + (size_t)(bn + row) * K + k0 + cc);
        }
        asm volatile("cp.async.commit_group;");
    };

    const int KT = K / BK;
    load_stage(0, 0);
    load_stage(1, BK);

    for (int kt = 0; kt < KT; ++kt) {
        asm volatile("cp.async.wait_group 1;");
        __syncthreads();   // single barrier per kt (3-stage ring makes tail sync redundant)
        const int cur = kt % NSTAGE;
        if (kt + 2 < KT) load_stage((kt + 2) % NSTAGE, (kt + 2) * BK);

        const uint32_t* As = sm + cur * 2 * STAGE_WORDS;
        const uint32_t* Bs = As + STAGE_WORDS;

        // Batch ALL fragment loads for both ks-steps (MLP ~48), then MMA burst.
        uint32_t af[2][4][4], bf[2][4][2];
        #pragma unroll
        for (int ks = 0; ks < 2; ++ks) {
            const int k0 = ks * 8;
            #pragma unroll
            for (int mi = 0; mi < 4; mi++) {
                const int r = wm + mi * 16 + g;
                af[ks][mi][0] = As[(r)     * BKP + k0 + t4];
                af[ks][mi][1] = As[(r + 8) * BKP + k0 + t4];
                af[ks][mi][2] = As[(r)     * BKP + k0 + t4 + 4];
                af[ks][mi][3] = As[(r + 8) * BKP + k0 + t4 + 4];
            }
            #pragma unroll
            for (int ni = 0; ni < 4; ni++) {
                const int r = wn + ni * 8 + g;
                bf[ks][ni][0] = Bs[r * BKP + k0 + t4];
                bf[ks][ni][1] = Bs[r * BKP + k0 + t4 + 4];
            }
        }
        #pragma unroll
        for (int ks = 0; ks < 2; ++ks)
            #pragma unroll
            for (int mi = 0; mi < 4; mi++)
                #pragma unroll
                for (int ni = 0; ni < 4; ni++)
                    mma_tf32(acc[mi][ni], af[ks][mi], bf[ks][ni]);
    }

    #pragma unroll
    for (int mi = 0; mi < 4; mi++) {
        #pragma unroll
        for (int ni = 0; ni < 4; ni++) {
            const size_t r0 = (size_t)(bm + wm + mi * 16 + g);
            const size_t c0 = (size_t)(bn + wn + ni * 8 + t4 * 2);
            *reinterpret_cast<float2*>(C + r0 * N + c0) =
                make_float2(acc[mi][ni][0], acc[mi][ni][1]);
            *reinterpret_cast<float2*>(C + (r0 + 8) * N + c0) =
                make_float2(acc[mi][ni][2], acc[mi][ni][3]);
        }
    }
}

// ── Chunked scan, 4 channels per thread (float4 streams) ────────────────
__global__ void __launch_bounds__(256)
scan_pass1(const float* __restrict__ cw) {
    const int q     = blockIdx.x * blockDim.x + threadIdx.x;   // 0..BC4*NC-1
    const int bcq   = q & (BC4 - 1);
    const int chunk = q >> 11;
    const int b  = bcq >> 9;            // /512
    const int c4 = bcq & 511;
    const int c  = c4 * 4;

    float4 w[4];                         // taps for channels c..c+3
    #pragma unroll
    for (int j = 0; j < 4; j++) w[j] = ((const float4*)cw)[c4 * 4 + j];

    const float* Yb = g_Y + (size_t)b * SEQ * N1;
    const float4* zp = (const float4*)(Yb + HID + c);
    const float4* hp = (const float4*)(Yb + 2 * HID + c);
    const int st4 = N1 / 4;

    const int s0 = chunk * CL;
    float4 z1 = {0,0,0,0}, z2 = {0,0,0,0}, z3 = {0,0,0,0};
    if (chunk > 0) {
        z1 = zp[(size_t)(s0 - 1) * st4];
        z2 = zp[(size_t)(s0 - 2) * st4];
        z3 = zp[(size_t)(s0 - 3) * st4];
    }
    float4 A = {1,1,1,1}, B = {0,0,0,0};
    #pragma unroll 4
    for (int s = s0; s < s0 + CL; ++s) {
        const float4 zr  = zp[(size_t)s * st4];
        const float4 hin = hp[(size_t)s * st4];
        float cv, zt, a;
        #define STEP1(j, Z1, Z2, Z3, ZR, HIN, AA, BB)                         \
            cv = w[j].x * Z3 + w[j].y * Z2 + w[j].z * Z1 + w[j].w * ZR;       \
            zt = sigmoidf_fast(cv); a = 1.f - zt;                             \
            AA *= a; BB = fmaf(a, BB, zt * HIN);
        STEP1(0, z1.x, z2.x, z3.x, zr.x, hin.x, A.x, B.x)
        STEP1(1, z1.y, z2.y, z3.y, zr.y, hin.y, A.y, B.y)
        STEP1(2, z1.z, z2.z, z3.z, zr.z, hin.z, A.z, B.z)
        STEP1(3, z1.w, z2.w, z3.w, zr.w, hin.w, A.w, B.w)
        #undef STEP1
        z3 = z2; z2 = z1; z1 = zr;
    }
    const int vi = (chunk * BC + b * HID + c) / 4;
    ((float4*)g_A)[vi] = A;
    ((float4*)g_B)[vi] = B;
}

__global__ void __launch_bounds__(256)
scan_combine() {
    const int bc = blockIdx.x * blockDim.x + threadIdx.x;
    float h = 0.f;
    #pragma unroll
    for (int i = 0; i < NC; ++i) {
        g_H[i * BC + bc] = h;
        h = fmaf(g_A[i * BC + bc], h, g_B[i * BC + bc]);
    }
}

__global__ void __launch_bounds__(256)
scan_pass2(const float* __restrict__ cw, uint32_t* __restrict__ O) {
    const int q     = blockIdx.x * blockDim.x + threadIdx.x;
    const int bcq   = q & (BC4 - 1);
    const int chunk = q >> 11;
    const int b  = bcq >> 9;
    const int c4 = bcq & 511;
    const int c  = c4 * 4;

    float4 w[4];
    #pragma unroll
    for (int j = 0; j < 4; j++) w[j] = ((const float4*)cw)[c4 * 4 + j];

    const float* Yb = g_Y + (size_t)b * SEQ * N1;
    const float4* o1p = (const float4*)(Yb + c);
    const float4* zp  = (const float4*)(Yb + HID + c);
    const float4* hp  = (const float4*)(Yb + 2 * HID + c);
    uint4* outp = (uint4*)(O + (size_t)b * SEQ * HID + c);
    const int st4 = N1 / 4;
    const int so4 = HID / 4;

    const int s0 = chunk * CL;
    float4 z1 = {0,0,0,0}, z2 = {0,0,0,0}, z3 = {0,0,0,0};
    if (chunk > 0) {
        z1 = zp[(size_t)(s0 - 1) * st4];
        z2 = zp[(size_t)(s0 - 2) * st4];
        z3 = zp[(size_t)(s0 - 3) * st4];
    }
    float4 h = ((const float4*)g_H)[(chunk * BC + b * HID + c) / 4];
    #pragma unroll 4
    for (int s = s0; s < s0 + CL; ++s) {
        const float4 zr  = zp[(size_t)s * st4];
        const float4 hin = hp[(size_t)s * st4];
        const float4 o1  = o1p[(size_t)s * st4];
        uint4 ov;
        float cv, zt, sil;
        #define STEP2(j, Z1, Z2, Z3, ZR, HIN, O1, HH, OV)                      \
            cv = w[j].x * Z3 + w[j].y * Z2 + w[j].z * Z1 + w[j].w * ZR;        \
            zt = sigmoidf_fast(cv);                                            \
            HH = fmaf(zt, HIN - HH, HH);                                       \
            sil = O1 * sigmoidf_fast(O1);                                      \
            OV = f2tf(sil * HH);
        STEP2(0, z1.x, z2.x, z3.x, zr.x, hin.x, o1.x, h.x, ov.x)
        STEP2(1, z1.y, z2.y, z3.y, zr.y, hin.y, o1.y, h.y, ov.y)
        STEP2(2, z1.z, z2.z, z3.z, zr.z, hin.z, o1.z, h.z, ov.z)
        STEP2(3, z1.w, z2.w, z3.w, zr.w, hin.w, o1.w, h.w, ov.w)
        #undef STEP2
        z3 = z2; z2 = z1; z1 = zr;
        outp[(size_t)s * so4] = ov;
    }
}

extern "C" void kernel_launch(void* const* d_in, const int* in_sizes, int n_in,
                              void* d_out, int out_size) {
    const float* x  = (const float*)d_in[0];
    const float* w1 = (const float*)d_in[1];
    const float* w2 = (const float*)d_in[2];
    const float* cw = (const float*)d_in[3];
    float* out = (float*)d_out;

    float *Y;
    uint32_t *O, *X, *W1, *W2;
    cudaGetSymbolAddress((void**)&Y,  g_Y);
    cudaGetSymbolAddress((void**)&O,  g_O);
    cudaGetSymbolAddress((void**)&X,  g_X);
    cudaGetSymbolAddress((void**)&W1, g_W1);
    cudaGetSymbolAddress((void**)&W2, g_W2);

    static bool attr_set = false;
    if (!attr_set) {
        cudaFuncSetAttribute(gemm_tn_tf32,
                             cudaFuncAttributeMaxDynamicSharedMemorySize, SMEM_DYN);
        attr_set = true;
    }

    // Pre-convert GEMM operands to tf32
    {
        int n4;
        n4 = (MROWS * EMB) / 4;
        cvt_tf32_kernel<<<(n4 + 255) / 256, 256>>>((const float4*)x,  (uint4*)X,  n4);
        n4 = (N1 * EMB) / 4;
        cvt_tf32_kernel<<<(n4 + 255) / 256, 256>>>((const float4*)w1, (uint4*)W1, n4);
        n4 = (EMB * HID) / 4;
        cvt_tf32_kernel<<<(n4 + 255) / 256, 256>>>((const float4*)w2, (uint4*)W2, n4);
    }

    // GEMM1
    dim3 g1(N1 / BN, MROWS / BM);
    gemm_tn_tf32<<<g1, 256, SMEM_DYN>>>(X, W1, Y, MROWS, N1, EMB);

    // Chunked scan (vectorized 4-wide)
    scan_pass1<<<(BC4 * NC) / 256, 256>>>(cw);
    scan_combine<<<BC / 256, 256>>>();
    scan_pass2<<<(BC4 * NC) / 256, 256>>>(cw, O);

    // GEMM2
    dim3 g2(EMB / BN, MROWS / BM);
    gemm_tn_tf32<<<g2, 256, SMEM_DYN>>>(O, W2, out, MROWS, EMB, HID);
}

// round 13
// speedup vs baseline: 3.5691x; 1.7304x over previous
#include <cuda_runtime.h>
#include <cuda_fp16.h>
#include <cstdint>

// Problem constants
#define BATCH 4
#define SEQ   2048
#define EMB   1024
#define HID   2048
#define N1    (3*HID)          // 6144
#define MROWS (BATCH*SEQ)      // 8192
#define BC    (BATCH*HID)      // 8192
#define NC    32               // scan chunks
#define CL    (SEQ/NC)         // 64
#define BC4   (BC/4)           // 2048 vector lanes

// GEMM tiling (fp16 path)
#define BM 128
#define BN 128
#define BKH 32                 // halves of K per kt tile
#define BKPH 40                // padded smem row stride in halves (80 B)
#define NSTAGE 3
#define STAGE_HALVES (BM * BKPH)                    // per-operand halves per stage
#define SMEM_DYN (NSTAGE * 2 * STAGE_HALVES * 2)    // 61440 B

// Scratch (allocation-free rule: __device__ globals)
__device__ float  g_Y[(size_t)MROWS * N1];
__device__ __half g_O[(size_t)MROWS * HID];
__device__ __half g_X[(size_t)MROWS * EMB];
__device__ __half g_W1[(size_t)N1 * EMB];
__device__ __half g_W2[(size_t)EMB * HID];
__device__ float g_A[NC * BC];
__device__ float g_B[NC * BC];
__device__ float g_H[NC * BC];

__device__ __forceinline__ void cp_async16(uint32_t saddr, const void* gptr) {
    asm volatile("cp.async.cg.shared.global [%0], [%1], 16;" :: "r"(saddr), "l"(gptr));
}
__device__ __forceinline__ void mma_f16(float c[4], const uint32_t a[4], const uint32_t b[2]) {
    asm volatile(
        "mma.sync.aligned.m16n8k16.row.col.f32.f16.f16.f32 "
        "{%0,%1,%2,%3}, {%4,%5,%6,%7}, {%8,%9}, {%0,%1,%2,%3};"
        : "+f"(c[0]), "+f"(c[1]), "+f"(c[2]), "+f"(c[3])
        : "r"(a[0]), "r"(a[1]), "r"(a[2]), "r"(a[3]), "r"(b[0]), "r"(b[1]));
}
__device__ __forceinline__ float sigmoidf_fast(float x) {
    return 1.f / (1.f + __expf(-x));
}

// ── f32 -> f16 bulk convert ─────────────────────────────────────────────
__global__ void __launch_bounds__(256)
cvt_f16_kernel(const float4* __restrict__ in, uint2* __restrict__ out, int n4) {
    int i = blockIdx.x * blockDim.x + threadIdx.x;
    if (i < n4) {
        float4 v = in[i];
        __half2 lo = __floats2half2_rn(v.x, v.y);
        __half2 hi = __floats2half2_rn(v.z, v.w);
        uint2 o;
        o.x = *reinterpret_cast<uint32_t*>(&lo);
        o.y = *reinterpret_cast<uint32_t*>(&hi);
        out[i] = o;
    }
}

// ── fp16 GEMM: C[M,N] = A[M,K] · B[N,K]^T (K-major halves) ──────────────
__global__ void __launch_bounds__(256, 2)
gemm_tn_f16(const __half* __restrict__ A, const __half* __restrict__ B,
            float* __restrict__ C, int M, int N, int K) {
    extern __shared__ __align__(16) __half smh[];
    const int tid  = threadIdx.x;
    const int lane = tid & 31;
    const int warp = tid >> 5;
    const int bm = blockIdx.y * BM;
    const int bn = blockIdx.x * BN;
    const int wm = (warp & 1) * 64;
    const int wn = (warp >> 1) * 32;
    const int g  = lane >> 2;
    const int t4 = lane & 3;

    float acc[4][4][4];
    #pragma unroll
    for (int i = 0; i < 4; i++)
        #pragma unroll
        for (int j = 0; j < 4; j++)
            #pragma unroll
            for (int r = 0; r < 4; r++) acc[i][j][r] = 0.f;

    auto load_stage = [&](int stage, int k0) {
        __half* As = smh + stage * 2 * STAGE_HALVES;
        __half* Bs = As + STAGE_HALVES;
        // per operand: 128 rows * 64B = 512 chunks of 16B; 2 chunks/thread each
        #pragma unroll
        for (int i = 0; i < 2; i++) {
            int ci  = tid + i * 256;           // 0..511
            int row = ci >> 2;                 // 4 chunks per row
            int cc  = (ci & 3) * 8;            // halves
            cp_async16(__cvta_generic_to_shared(&As[row * BKPH + cc]),
                       A + (size_t)(bm + row) * K + k0 + cc);
            cp_async16(__cvta_generic_to_shared(&Bs[row * BKPH + cc]),
                       B + (size_t)(bn + row) * K + k0 + cc);
        }
        asm volatile("cp.async.commit_group;");
    };

    const int KT = K / BKH;
    load_stage(0, 0);
    load_stage(1, BKH);

    for (int kt = 0; kt < KT; ++kt) {
        asm volatile("cp.async.wait_group 1;");
        __syncthreads();
        const int cur = kt % NSTAGE;
        if (kt + 2 < KT) load_stage((kt + 2) % NSTAGE, (kt + 2) * BKH);

        const uint32_t* As32 = reinterpret_cast<const uint32_t*>(smh + cur * 2 * STAGE_HALVES);
        const uint32_t* Bs32 = As32 + STAGE_HALVES / 2;
        // row stride in u32 = BKPH/2 = 20

        #pragma unroll
        for (int ks = 0; ks < 2; ++ks) {
            const int k0 = ks * 8;             // in u32 units (16 halves)
            uint32_t af[4][4], bf[4][2];
            #pragma unroll
            for (int mi = 0; mi < 4; mi++) {
                const int r = wm + mi * 16 + g;
                af[mi][0] = As32[(r)     * 20 + k0 + t4];
                af[mi][1] = As32[(r + 8) * 20 + k0 + t4];
                af[mi][2] = As32[(r)     * 20 + k0 + t4 + 4];
                af[mi][3] = As32[(r + 8) * 20 + k0 + t4 + 4];
            }
            #pragma unroll
            for (int ni = 0; ni < 4; ni++) {
                const int r = wn + ni * 8 + g;
                bf[ni][0] = Bs32[r * 20 + k0 + t4];
                bf[ni][1] = Bs32[r * 20 + k0 + t4 + 4];
            }
            #pragma unroll
            for (int mi = 0; mi < 4; mi++)
                #pragma unroll
                for (int ni = 0; ni < 4; ni++)
                    mma_f16(acc[mi][ni], af[mi], bf[ni]);
        }
    }

    #pragma unroll
    for (int mi = 0; mi < 4; mi++) {
        #pragma unroll
        for (int ni = 0; ni < 4; ni++) {
            const size_t r0 = (size_t)(bm + wm + mi * 16 + g);
            const size_t c0 = (size_t)(bn + wn + ni * 8 + t4 * 2);
            *reinterpret_cast<float2*>(C + r0 * N + c0) =
                make_float2(acc[mi][ni][0], acc[mi][ni][1]);
            *reinterpret_cast<float2*>(C + (r0 + 8) * N + c0) =
                make_float2(acc[mi][ni][2], acc[mi][ni][3]);
        }
    }
}

// ── Chunked scan, 4 channels per thread (float4 streams) ────────────────
__global__ void __launch_bounds__(256)
scan_pass1(const float* __restrict__ cw) {
    const int q     = blockIdx.x * blockDim.x + threadIdx.x;
    const int bcq   = q & (BC4 - 1);
    const int chunk = q >> 11;
    const int b  = bcq >> 9;
    const int c4 = bcq & 511;
    const int c  = c4 * 4;

    float4 w[4];
    #pragma unroll
    for (int j = 0; j < 4; j++) w[j] = ((const float4*)cw)[c4 * 4 + j];

    const float* Yb = g_Y + (size_t)b * SEQ * N1;
    const float4* zp = (const float4*)(Yb + HID + c);
    const float4* hp = (const float4*)(Yb + 2 * HID + c);
    const int st4 = N1 / 4;

    const int s0 = chunk * CL;
    float4 z1 = {0,0,0,0}, z2 = {0,0,0,0}, z3 = {0,0,0,0};
    if (chunk > 0) {
        z1 = zp[(size_t)(s0 - 1) * st4];
        z2 = zp[(size_t)(s0 - 2) * st4];
        z3 = zp[(size_t)(s0 - 3) * st4];
    }
    float4 A = {1,1,1,1}, B = {0,0,0,0};
    #pragma unroll 4
    for (int s = s0; s < s0 + CL; ++s) {
        const float4 zr  = zp[(size_t)s * st4];
        const float4 hin = hp[(size_t)s * st4];
        float cv, zt, a;
        #define STEP1(j, Z1, Z2, Z3, ZR, HIN, AA, BB)                         \
            cv = w[j].x * Z3 + w[j].y * Z2 + w[j].z * Z1 + w[j].w * ZR;       \
            zt = sigmoidf_fast(cv); a = 1.f - zt;                             \
            AA *= a; BB = fmaf(a, BB, zt * HIN);
        STEP1(0, z1.x, z2.x, z3.x, zr.x, hin.x, A.x, B.x)
        STEP1(1, z1.y, z2.y, z3.y, zr.y, hin.y, A.y, B.y)
        STEP1(2, z1.z, z2.z, z3.z, zr.z, hin.z, A.z, B.z)
        STEP1(3, z1.w, z2.w, z3.w, zr.w, hin.w, A.w, B.w)
        #undef STEP1
        z3 = z2; z2 = z1; z1 = zr;
    }
    const int vi = (chunk * BC + b * HID + c) / 4;
    ((float4*)g_A)[vi] = A;
    ((float4*)g_B)[vi] = B;
}

__global__ void __launch_bounds__(256)
scan_combine() {
    const int bc = blockIdx.x * blockDim.x + threadIdx.x;
    float h = 0.f;
    #pragma unroll
    for (int i = 0; i < NC; ++i) {
        g_H[i * BC + bc] = h;
        h = fmaf(g_A[i * BC + bc], h, g_B[i * BC + bc]);
    }
}

__global__ void __launch_bounds__(256)
scan_pass2(const float* __restrict__ cw, __half* __restrict__ O) {
    const int q     = blockIdx.x * blockDim.x + threadIdx.x;
    const int bcq   = q & (BC4 - 1);
    const int chunk = q >> 11;
    const int b  = bcq >> 9;
    const int c4 = bcq & 511;
    const int c  = c4 * 4;

    float4 w[4];
    #pragma unroll
    for (int j = 0; j < 4; j++) w[j] = ((const float4*)cw)[c4 * 4 + j];

    const float* Yb = g_Y + (size_t)b * SEQ * N1;
    const float4* o1p = (const float4*)(Yb + c);
    const float4* zp  = (const float4*)(Yb + HID + c);
    const float4* hp  = (const float4*)(Yb + 2 * HID + c);
    uint2* outp = (uint2*)(O + (size_t)b * SEQ * HID + c);
    const int st4 = N1 / 4;
    const int so2 = HID / 4;   // uint2 stride per step

    const int s0 = chunk * CL;
    float4 z1 = {0,0,0,0}, z2 = {0,0,0,0}, z3 = {0,0,0,0};
    if (chunk > 0) {
        z1 = zp[(size_t)(s0 - 1) * st4];
        z2 = zp[(size_t)(s0 - 2) * st4];
        z3 = zp[(size_t)(s0 - 3) * st4];
    }
    float4 h = ((const float4*)g_H)[(chunk * BC + b * HID + c) / 4];
    #pragma unroll 4
    for (int s = s0; s < s0 + CL; ++s) {
        const float4 zr  = zp[(size_t)s * st4];
        const float4 hin = hp[(size_t)s * st4];
        const float4 o1  = o1p[(size_t)s * st4];
        float4 ov;
        float cv, zt, sil;
        #define STEP2(j, Z1, Z2, Z3, ZR, HIN, O1, HH, OV)                      \
            cv = w[j].x * Z3 + w[j].y * Z2 + w[j].z * Z1 + w[j].w * ZR;        \
            zt = sigmoidf_fast(cv);                                            \
            HH = fmaf(zt, HIN - HH, HH);                                       \
            sil = O1 * sigmoidf_fast(O1);                                      \
            OV = sil * HH;
        STEP2(0, z1.x, z2.x, z3.x, zr.x, hin.x, o1.x, h.x, ov.x)
        STEP2(1, z1.y, z2.y, z3.y, zr.y, hin.y, o1.y, h.y, ov.y)
        STEP2(2, z1.z, z2.z, z3.z, zr.z, hin.z, o1.z, h.z, ov.z)
        STEP2(3, z1.w, z2.w, z3.w, zr.w, hin.w, o1.w, h.w, ov.w)
        #undef STEP2
        z3 = z2; z2 = z1; z1 = zr;
        __half2 lo = __floats2half2_rn(ov.x, ov.y);
        __half2 hi = __floats2half2_rn(ov.z, ov.w);
        uint2 u;
        u.x = *reinterpret_cast<uint32_t*>(&lo);
        u.y = *reinterpret_cast<uint32_t*>(&hi);
        outp[(size_t)s * so2] = u;
    }
}

extern "C" void kernel_launch(void* const* d_in, const int* in_sizes, int n_in,
                              void* d_out, int out_size) {
    const float* x  = (const float*)d_in[0];
    const float* w1 = (const float*)d_in[1];
    const float* w2 = (const float*)d_in[2];
    const float* cw = (const float*)d_in[3];
    float* out = (float*)d_out;

    float *Y;
    __half *O, *X, *W1, *W2;
    cudaGetSymbolAddress((void**)&Y,  g_Y);
    cudaGetSymbolAddress((void**)&O,  g_O);
    cudaGetSymbolAddress((void**)&X,  g_X);
    cudaGetSymbolAddress((void**)&W1, g_W1);
    cudaGetSymbolAddress((void**)&W2, g_W2);

    static bool attr_set = false;
    if (!attr_set) {
        cudaFuncSetAttribute(gemm_tn_f16,
                             cudaFuncAttributeMaxDynamicSharedMemorySize, SMEM_DYN);
        attr_set = true;
    }

    // Pre-convert GEMM operands to fp16
    {
        int n4;
        n4 = (MROWS * EMB) / 4;
        cvt_f16_kernel<<<(n4 + 255) / 256, 256>>>((const float4*)x,  (uint2*)X,  n4);
        n4 = (N1 * EMB) / 4;
        cvt_f16_kernel<<<(n4 + 255) / 256, 256>>>((const float4*)w1, (uint2*)W1, n4);
        n4 = (EMB * HID) / 4;
        cvt_f16_kernel<<<(n4 + 255) / 256, 256>>>((const float4*)w2, (uint2*)W2, n4);
    }

    // GEMM1: Y[8192,6144] = x @ w1^T
    dim3 g1(N1 / BN, MROWS / BM);
    gemm_tn_f16<<<g1, 256, SMEM_DYN>>>(X, W1, Y, MROWS, N1, EMB);

    // Chunked scan
    scan_pass1<<<(BC4 * NC) / 256, 256>>>(cw);
    scan_combine<<<BC / 256, 256>>>();
    scan_pass2<<<(BC4 * NC) / 256, 256>>>(cw, O);

    // GEMM2: out[8192,1024] = O @ w2^T
    dim3 g2(EMB / BN, MROWS / BM);
    gemm_tn_f16<<<g2, 256, SMEM_DYN>>>(O, W2, out, MROWS, EMB, HID);
}

// round 16
// speedup vs baseline: 3.9601x; 1.1095x over previous
#include <cuda_runtime.h>
#include <cuda_fp16.h>
#include <cstdint>

// Problem constants
#define BATCH 4
#define SEQ   2048
#define EMB   1024
#define HID   2048
#define N1    (3*HID)          // 6144
#define MROWS (BATCH*SEQ)      // 8192
#define BC    (BATCH*HID)      // 8192
#define NC    32               // scan chunks
#define CL    (SEQ/NC)         // 64
#define BC4   (BC/4)           // 2048 vector lanes

// GEMM tiling (fp16 path)
#define BM 128
#define BN 128
#define BKH 32                 // halves of K per kt tile
#define BKPH 40                // padded smem row stride in halves (80 B)
#define NSTAGE 3
#define STAGE_HALVES (BM * BKPH)
#define STAGE_BYTES  (2 * STAGE_HALVES * 2)         // A+B per stage (20480 B)
#define BOFF_BYTES   (STAGE_HALVES * 2)             // B region offset in stage
#define SMEM_DYN (NSTAGE * STAGE_BYTES)             // 61440 B

// Scratch (allocation-free rule: __device__ globals)
__device__ float  g_Y[(size_t)MROWS * N1];
__device__ __half g_O[(size_t)MROWS * HID];
__device__ __half g_X[(size_t)MROWS * EMB];
__device__ __half g_W1[(size_t)N1 * EMB];
__device__ __half g_W2[(size_t)EMB * HID];
__device__ float g_A[NC * BC];
__device__ float g_B[NC * BC];
__device__ float g_H[NC * BC];

__device__ __forceinline__ void cp_async16(uint32_t saddr, const void* gptr) {
    asm volatile("cp.async.cg.shared.global [%0], [%1], 16;" :: "r"(saddr), "l"(gptr));
}
__device__ __forceinline__ void mma_f16(float c[4], const uint32_t a[4],
                                        uint32_t b0, uint32_t b1) {
    asm volatile(
        "mma.sync.aligned.m16n8k16.row.col.f32.f16.f16.f32 "
        "{%0,%1,%2,%3}, {%4,%5,%6,%7}, {%8,%9}, {%0,%1,%2,%3};"
        : "+f"(c[0]), "+f"(c[1]), "+f"(c[2]), "+f"(c[3])
        : "r"(a[0]), "r"(a[1]), "r"(a[2]), "r"(a[3]), "r"(b0), "r"(b1));
}
__device__ __forceinline__ void ldsm_x4(uint32_t& r0, uint32_t& r1, uint32_t& r2,
                                        uint32_t& r3, uint32_t addr) {
    asm volatile("ldmatrix.sync.aligned.m8n8.x4.shared.b16 {%0,%1,%2,%3}, [%4];"
                 : "=r"(r0), "=r"(r1), "=r"(r2), "=r"(r3) : "r"(addr));
}
__device__ __forceinline__ float sigmoidf_fast(float x) {
    return 1.f / (1.f + __expf(-x));
}

// ── f32 -> f16 bulk convert ─────────────────────────────────────────────
__global__ void __launch_bounds__(256)
cvt_f16_kernel(const float4* __restrict__ in, uint2* __restrict__ out, int n4) {
    int i = blockIdx.x * blockDim.x + threadIdx.x;
    if (i < n4) {
        float4 v = in[i];
        __half2 lo = __floats2half2_rn(v.x, v.y);
        __half2 hi = __floats2half2_rn(v.z, v.w);
        uint2 o;
        o.x = *reinterpret_cast<uint32_t*>(&lo);
        o.y = *reinterpret_cast<uint32_t*>(&hi);
        out[i] = o;
    }
}

// ── fp16 GEMM: C[M,N] = A[M,K] · B[N,K]^T (K-major halves) ──────────────
__global__ void __launch_bounds__(256, 2)
gemm_tn_f16(const __half* __restrict__ A, const __half* __restrict__ B,
            float* __restrict__ C, int M, int N, int K) {
    extern __shared__ __align__(16) __half smh[];
    const int tid  = threadIdx.x;
    const int lane = tid & 31;
    const int warp = tid >> 5;
    const int bm = blockIdx.y * BM;
    const int bn = blockIdx.x * BN;
    const int wm = (warp & 1) * 64;
    const int wn = (warp >> 1) * 32;
    const int g  = lane >> 2;
    const int t4 = lane & 3;

    float acc[4][4][4];
    #pragma unroll
    for (int i = 0; i < 4; i++)
        #pragma unroll
        for (int j = 0; j < 4; j++)
            #pragma unroll
            for (int r = 0; r < 4; r++) acc[i][j][r] = 0.f;

    const uint32_t smem0 = (uint32_t)__cvta_generic_to_shared(smh);
    // ldmatrix per-lane offsets (bytes), row stride = 80 B
    // A: m0=rows0-7@k0, m1=rows8-15@k0, m2=rows0-7@k8, m3=rows8-15@k8
    const uint32_t aoff = (uint32_t)(wm + (lane & 15)) * 80u + ((lane & 16) ? 16u : 0u);
    // B: m0=n0-7@k0, m1=n0-7@k8, m2=n8-15@k0, m3=n8-15@k8
    const uint32_t boff = (uint32_t)(wn + (lane & 7) + ((lane >> 4) & 1) * 8) * 80u
                        + (((lane >> 3) & 1) ? 16u : 0u) + BOFF_BYTES;

    auto load_stage = [&](int stage, int k0) {
        __half* As = smh + stage * 2 * STAGE_HALVES;
        __half* Bs = As + STAGE_HALVES;
        #pragma unroll
        for (int i = 0; i < 2; i++) {
            int ci  = tid + i * 256;           // 0..511
            int row = ci >> 2;
            int cc  = (ci & 3) * 8;            // halves
            cp_async16(__cvta_generic_to_shared(&As[row * BKPH + cc]),
                       A + (size_t)(bm + row) * K + k0 + cc);
            cp_async16(__cvta_generic_to_shared(&Bs[row * BKPH + cc]),
                       B + (size_t)(bn + row) * K + k0 + cc);
        }
        asm volatile("cp.async.commit_group;");
    };

    const int KT = K / BKH;
    load_stage(0, 0);
    load_stage(1, BKH);

    for (int kt = 0; kt < KT; ++kt) {
        asm volatile("cp.async.wait_group 1;");
        __syncthreads();
        const int cur = kt % NSTAGE;
        if (kt + 2 < KT) load_stage((kt + 2) % NSTAGE, (kt + 2) * BKH);

        const uint32_t abase = smem0 + cur * STAGE_BYTES + aoff;
        const uint32_t bbase = smem0 + cur * STAGE_BYTES + boff;

        #pragma unroll
        for (int ks = 0; ks < 2; ++ks) {
            const uint32_t kb = ks * 32;       // 16 halves = 32 B
            uint32_t a[4][4], br[2][4];
            #pragma unroll
            for (int mi = 0; mi < 4; mi++)
                ldsm_x4(a[mi][0], a[mi][1], a[mi][2], a[mi][3],
                        abase + mi * (16 * 80) + kb);
            #pragma unroll
            for (int j = 0; j < 2; j++)
                ldsm_x4(br[j][0], br[j][1], br[j][2], br[j][3],
                        bbase + j * (16 * 80) + kb);
            #pragma unroll
            for (int mi = 0; mi < 4; mi++) {
                #pragma unroll
                for (int j = 0; j < 2; j++) {
                    mma_f16(acc[mi][2*j],   a[mi], br[j][0], br[j][1]);
                    mma_f16(acc[mi][2*j+1], a[mi], br[j][2], br[j][3]);
                }
            }
        }
    }

    #pragma unroll
    for (int mi = 0; mi < 4; mi++) {
        #pragma unroll
        for (int ni = 0; ni < 4; ni++) {
            const size_t r0 = (size_t)(bm + wm + mi * 16 + g);
            const size_t c0 = (size_t)(bn + wn + ni * 8 + t4 * 2);
            *reinterpret_cast<float2*>(C + r0 * N + c0) =
                make_float2(acc[mi][ni][0], acc[mi][ni][1]);
            *reinterpret_cast<float2*>(C + (r0 + 8) * N + c0) =
                make_float2(acc[mi][ni][2], acc[mi][ni][3]);
        }
    }
}

// ── Chunked scan, 4 channels per thread (float4 streams) ────────────────
__global__ void __launch_bounds__(256)
scan_pass1(const float* __restrict__ cw) {
    const int q     = blockIdx.x * blockDim.x + threadIdx.x;
    const int bcq   = q & (BC4 - 1);
    const int chunk = q >> 11;
    const int b  = bcq >> 9;
    const int c4 = bcq & 511;
    const int c  = c4 * 4;

    float4 w[4];
    #pragma unroll
    for (int j = 0; j < 4; j++) w[j] = ((const float4*)cw)[c4 * 4 + j];

    const float* Yb = g_Y + (size_t)b * SEQ * N1;
    const float4* zp = (const float4*)(Yb + HID + c);
    const float4* hp = (const float4*)(Yb + 2 * HID + c);
    const int st4 = N1 / 4;

    const int s0 = chunk * CL;
    float4 z1 = {0,0,0,0}, z2 = {0,0,0,0}, z3 = {0,0,0,0};
    if (chunk > 0) {
        z1 = zp[(size_t)(s0 - 1) * st4];
        z2 = zp[(size_t)(s0 - 2) * st4];
        z3 = zp[(size_t)(s0 - 3) * st4];
    }
    float4 A = {1,1,1,1}, B = {0,0,0,0};
    #pragma unroll 4
    for (int s = s0; s < s0 + CL; ++s) {
        const float4 zr  = zp[(size_t)s * st4];
        const float4 hin = hp[(size_t)s * st4];
        float cv, zt, a;
        #define STEP1(j, Z1, Z2, Z3, ZR, HIN, AA, BB)                         \
            cv = w[j].x * Z3 + w[j].y * Z2 + w[j].z * Z1 + w[j].w * ZR;       \
            zt = sigmoidf_fast(cv); a = 1.f - zt;                             \
            AA *= a; BB = fmaf(a, BB, zt * HIN);
        STEP1(0, z1.x, z2.x, z3.x, zr.x, hin.x, A.x, B.x)
        STEP1(1, z1.y, z2.y, z3.y, zr.y, hin.y, A.y, B.y)
        STEP1(2, z1.z, z2.z, z3.z, zr.z, hin.z, A.z, B.z)
        STEP1(3, z1.w, z2.w, z3.w, zr.w, hin.w, A.w, B.w)
        #undef STEP1
        z3 = z2; z2 = z1; z1 = zr;
    }
    const int vi = (chunk * BC + b * HID + c) / 4;
    ((float4*)g_A)[vi] = A;
    ((float4*)g_B)[vi] = B;
}

__global__ void __launch_bounds__(256)
scan_combine() {
    const int bc = blockIdx.x * blockDim.x + threadIdx.x;
    float h = 0.f;
    #pragma unroll
    for (int i = 0; i < NC; ++i) {
        g_H[i * BC + bc] = h;
        h = fmaf(g_A[i * BC + bc], h, g_B[i * BC + bc]);
    }
}

__global__ void __launch_bounds__(256)
scan_pass2(const float* __restrict__ cw, __half* __restrict__ O) {
    const int q     = blockIdx.x * blockDim.x + threadIdx.x;
    const int bcq   = q & (BC4 - 1);
    const int chunk = q >> 11;
    const int b  = bcq >> 9;
    const int c4 = bcq & 511;
    const int c  = c4 * 4;

    float4 w[4];
    #pragma unroll
    for (int j = 0; j < 4; j++) w[j] = ((const float4*)cw)[c4 * 4 + j];

    const float* Yb = g_Y + (size_t)b * SEQ * N1;
    const float4* o1p = (const float4*)(Yb + c);
    const float4* zp  = (const float4*)(Yb + HID + c);
    const float4* hp  = (const float4*)(Yb + 2 * HID + c);
    uint2* outp = (uint2*)(O + (size_t)b * SEQ * HID + c);
    const int st4 = N1 / 4;
    const int so2 = HID / 4;

    const int s0 = chunk * CL;
    float4 z1 = {0,0,0,0}, z2 = {0,0,0,0}, z3 = {0,0,0,0};
    if (chunk > 0) {
        z1 = zp[(size_t)(s0 - 1) * st4];
        z2 = zp[(size_t)(s0 - 2) * st4];
        z3 = zp[(size_t)(s0 - 3) * st4];
    }
    float4 h = ((const float4*)g_H)[(chunk * BC + b * HID + c) / 4];
    #pragma unroll 4
    for (int s = s0; s < s0 + CL; ++s) {
        const float4 zr  = zp[(size_t)s * st4];
        const float4 hin = hp[(size_t)s * st4];
        const float4 o1  = o1p[(size_t)s * st4];
        float4 ov;
        float cv, zt, sil;
        #define STEP2(j, Z1, Z2, Z3, ZR, HIN, O1, HH, OV)                      \
            cv = w[j].x * Z3 + w[j].y * Z2 + w[j].z * Z1 + w[j].w * ZR;        \
            zt = sigmoidf_fast(cv);                                            \
            HH = fmaf(zt, HIN - HH, HH);                                       \
            sil = O1 * sigmoidf_fast(O1);                                      \
            OV = sil * HH;
        STEP2(0, z1.x, z2.x, z3.x, zr.x, hin.x, o1.x, h.x, ov.x)
        STEP2(1, z1.y, z2.y, z3.y, zr.y, hin.y, o1.y, h.y, ov.y)
        STEP2(2, z1.z, z2.z, z3.z, zr.z, hin.z, o1.z, h.z, ov.z)
        STEP2(3, z1.w, z2.w, z3.w, zr.w, hin.w, o1.w, h.w, ov.w)
        #undef STEP2
        z3 = z2; z2 = z1; z1 = zr;
        __half2 lo = __floats2half2_rn(ov.x, ov.y);
        __half2 hi = __floats2half2_rn(ov.z, ov.w);
        uint2 u;
        u.x = *reinterpret_cast<uint32_t*>(&lo);
        u.y = *reinterpret_cast<uint32_t*>(&hi);
        outp[(size_t)s * so2] = u;
    }
}

extern "C" void kernel_launch(void* const* d_in, const int* in_sizes, int n_in,
                              void* d_out, int out_size) {
    const float* x  = (const float*)d_in[0];
    const float* w1 = (const float*)d_in[1];
    const float* w2 = (const float*)d_in[2];
    const float* cw = (const float*)d_in[3];
    float* out = (float*)d_out;

    float *Y;
    __half *O, *X, *W1, *W2;
    cudaGetSymbolAddress((void**)&Y,  g_Y);
    cudaGetSymbolAddress((void**)&O,  g_O);
    cudaGetSymbolAddress((void**)&X,  g_X);
    cudaGetSymbolAddress((void**)&W1, g_W1);
    cudaGetSymbolAddress((void**)&W2, g_W2);

    static bool attr_set = false;
    if (!attr_set) {
        cudaFuncSetAttribute(gemm_tn_f16,
                             cudaFuncAttributeMaxDynamicSharedMemorySize, SMEM_DYN);
        attr_set = true;
    }

    // Pre-convert GEMM operands to fp16
    {
        int n4;
        n4 = (MROWS * EMB) / 4;
        cvt_f16_kernel<<<(n4 + 255) / 256, 256>>>((const float4*)x,  (uint2*)X,  n4);
        n4 = (N1 * EMB) / 4;
        cvt_f16_kernel<<<(n4 + 255) / 256, 256>>>((const float4*)w1, (uint2*)W1, n4);
        n4 = (EMB * HID) / 4;
        cvt_f16_kernel<<<(n4 + 255) / 256, 256>>>((const float4*)w2, (uint2*)W2, n4);
    }

    // GEMM1: Y[8192,6144] = x @ w1^T
    dim3 g1(N1 / BN, MROWS / BM);
    gemm_tn_f16<<<g1, 256, SMEM_DYN>>>(X, W1, Y, MROWS, N1, EMB);

    // Chunked scan
    scan_pass1<<<(BC4 * NC) / 256, 256>>>(cw);
    scan_combine<<<BC / 256, 256>>>();
    scan_pass2<<<(BC4 * NC) / 256, 256>>>(cw, O);

    // GEMM2: out[8192,1024] = O @ w2^T
    dim3 g2(EMB / BN, MROWS / BM);
    gemm_tn_f16<<<g2, 256, SMEM_DYN>>>(O, W2, out, MROWS, EMB, HID);
}